// round 11
// baseline (speedup 1.0000x reference)
#include <cuda_runtime.h>
#include <cuda_bf16.h>
#include <cstdint>

#define BQ 32
#define CC 256
#define HH 64
#define WW 64

// ---------------- static scratch ----------------
__device__ __nv_bfloat16 g_xh[(size_t)BQ*HH*WW*CC];   // relu(bn1(x)) NHWC hi
__device__ __nv_bfloat16 g_xl[(size_t)BQ*HH*WW*CC];   // lo
__device__ __nv_bfloat16 g_yh[(size_t)BQ*HH*WW*CC];   // conv1 out NHWC hi
__device__ __nv_bfloat16 g_yl[(size_t)BQ*HH*WW*CC];   // lo
__device__ __nv_bfloat16 g_w1h[(size_t)BQ*9*CC*CC];
__device__ __nv_bfloat16 g_w1l[(size_t)BQ*9*CC*CC];
__device__ __nv_bfloat16 g_w2h[(size_t)BQ*9*CC*CC];
__device__ __nv_bfloat16 g_w2l[(size_t)BQ*9*CC*CC];

// ---------------- helpers ----------------
__device__ __forceinline__ uint32_t smem_u32(const void* p) {
    uint32_t a;
    asm("{ .reg .u64 t; cvta.to.shared.u64 t, %1; cvt.u32.u64 %0, t; }" : "=r"(a) : "l"(p));
    return a;
}

// hi = truncated top 16 bits (exact bf16), lo = rn(v - hi). Packs (va,vb), va low.
__device__ __forceinline__ void split2(float va, float vb, uint32_t& hp, uint32_t& lp) {
    uint32_t ba = __float_as_uint(va), bb = __float_as_uint(vb);
    hp = __byte_perm(ba, bb, 0x7632);
    float la = va - __uint_as_float(ba & 0xFFFF0000u);
    float lb = vb - __uint_as_float(bb & 0xFFFF0000u);
    asm("cvt.rn.bf16x2.f32 %0, %1, %2;" : "=r"(lp) : "f"(lb), "f"(la));
}
// single-value split
__device__ __forceinline__ void split1(float v, uint16_t& h, uint16_t& l) {
    uint32_t b = __float_as_uint(v);
    h = (uint16_t)(b >> 16);
    float lf = v - __uint_as_float(b & 0xFFFF0000u);
    __nv_bfloat16 lb = __float2bfloat16_rn(lf);
    l = *(uint16_t*)&lb;
}

__device__ __forceinline__ void ldsm4(uint32_t* r, uint32_t addr) {
    asm volatile("ldmatrix.sync.aligned.m8n8.x4.shared.b16 {%0,%1,%2,%3}, [%4];"
                 : "=r"(r[0]), "=r"(r[1]), "=r"(r[2]), "=r"(r[3]) : "r"(addr));
}
__device__ __forceinline__ void mma16816(float* d, const uint32_t* a, const uint32_t* b) {
    asm volatile("mma.sync.aligned.m16n8k16.row.col.f32.bf16.bf16.f32 "
                 "{%0,%1,%2,%3}, {%4,%5,%6,%7}, {%8,%9}, {%0,%1,%2,%3};"
                 : "+f"(d[0]), "+f"(d[1]), "+f"(d[2]), "+f"(d[3])
                 : "r"(a[0]), "r"(a[1]), "r"(a[2]), "r"(a[3]), "r"(b[0]), "r"(b[1]));
}
#define CP16(dst, src)     asm volatile("cp.async.cg.shared.global [%0], [%1], 16;" :: "r"(dst), "l"(src))
#define CP16Z(dst, src, n) asm volatile("cp.async.cg.shared.global [%0], [%1], 16, %2;" :: "r"(dst), "l"(src), "r"(n))
#define CP_COMMIT()        asm volatile("cp.async.commit_group;" ::: "memory")
#define CP_WAIT0()         asm volatile("cp.async.wait_group 0;" ::: "memory")
#define CP_WAIT1()         asm volatile("cp.async.wait_group 1;" ::: "memory")

// ---------------- presynth: tw[b][khw][co][ci] = hb*w + bias, bf16 hi/lo ----
__global__ __launch_bounds__(288)
void presynth_kernel(const float* __restrict__ wv, const float* __restrict__ bv,
                     const float* __restrict__ hin,
                     __nv_bfloat16* __restrict__ oh, __nv_bfloat16* __restrict__ ol)
{
    __shared__ float sw[9*256];
    __shared__ float sbb[9*256];
    __shared__ float shb[8];
    const int co  = blockIdx.x;
    const int bg  = blockIdx.y;
    const int tid = threadIdx.x;

    for (int t = tid; t < 2304; t += 288) {
        int ciL = t / 9, khw = t - ciL * 9;
        sw[khw*256 + ciL]  = wv[co*2304 + t];
        sbb[khw*256 + ciL] = bv[co*2304 + t];
    }
    if (tid < 8) shb[tid] = 0.5f + hin[bg*8 + tid] * (1.0f/64.0f);
    __syncthreads();

    #pragma unroll 1
    for (int bi = 0; bi < 8; ++bi) {
        const int b = bg*8 + bi;
        const float hb = shb[bi];
        #pragma unroll
        for (int r = 0; r < 2; ++r) {
            int item = tid + r*288;
            int khw = item >> 6;
            int ci  = (item & 63) * 4;
            float4 w4 = *(const float4*)&sw[khw*256 + ci];
            float4 b4 = *(const float4*)&sbb[khw*256 + ci];
            float v0 = fmaf(hb, w4.x, b4.x);
            float v1 = fmaf(hb, w4.y, b4.y);
            float v2 = fmaf(hb, w4.z, b4.z);
            float v3 = fmaf(hb, w4.w, b4.w);
            uint32_t h0,l0,h1,l1;
            split2(v0, v1, h0, l0);
            split2(v2, v3, h1, l1);
            size_t o = (((size_t)b*9 + khw)*256 + co)*256 + ci;
            *(uint2*)(oh + o) = make_uint2(h0, h1);
            *(uint2*)(ol + o) = make_uint2(l0, l1);
        }
    }
}

// ---------------- prep: relu(bn1(x)) NCHW f32 -> NHWC bf16 hi/lo ----------
__global__ __launch_bounds__(256)
void prep_kernel(const float* __restrict__ x,
                 const float* __restrict__ g1, const float* __restrict__ be1,
                 const float* __restrict__ mu1, const float* __restrict__ var1,
                 __nv_bfloat16* __restrict__ xh, __nv_bfloat16* __restrict__ xl)
{
    __shared__ float sInv[256], sSh[256];
    __shared__ uint16_t th[64*72];      // [w][ci_l], row 144B
    __shared__ uint16_t tl[64*72];
    const int h   = blockIdx.x;
    const int b   = blockIdx.y;
    const int tid = threadIdx.x;

    {
        float inv = g1[tid] * rsqrtf(var1[tid] + 1e-5f);
        sInv[tid] = inv;
        sSh[tid]  = be1[tid] - mu1[tid] * inv;
    }
    __syncthreads();

    #pragma unroll 1
    for (int g4 = 0; g4 < 4; ++g4) {
        #pragma unroll 4
        for (int rep = 0; rep < 16; ++rep) {
            const int ci_l = rep*4 + (tid >> 6);
            const int ci   = g4*64 + ci_l;
            const int w    = tid & 63;
            float v = x[(((size_t)b*256 + ci)*64 + h)*64 + w];
            v = fmaxf(fmaf(v, sInv[ci], sSh[ci]), 0.f);
            uint16_t hh, ll;
            split1(v, hh, ll);
            th[w*72 + ci_l] = hh;
            tl[w*72 + ci_l] = ll;
        }
        __syncthreads();
        {
            const int w = tid >> 2, q = tid & 3;
            const size_t gofs = ((((size_t)b*64 + h)*64 + w)*256 + g4*64);
            const char* sh_ = (const char*)th + w*144 + q*32;
            const char* sl_ = (const char*)tl + w*144 + q*32;
            char* gh = (char*)(xh + gofs) + q*32;
            char* gl = (char*)(xl + gofs) + q*32;
            *(uint4*)(gh)      = *(const uint4*)(sh_);
            *(uint4*)(gh + 16) = *(const uint4*)(sh_ + 16);
            *(uint4*)(gl)      = *(const uint4*)(sl_);
            *(uint4*)(gl + 16) = *(const uint4*)(sl_ + 16);
        }
        __syncthreads();
    }
}

// ---------------- mma.sync implicit-GEMM hyperconv, cp.async 3-stage -------
#define SROWB 144
#define AHI_O 0
#define ALO_O 18432
#define BHI_O 36864
#define BLO_O 55296
#define BUFSZ 73728
#define NSTG  3
#define SMEM_TOT (NSTG*BUFSZ)           // 221184 B

__global__ __launch_bounds__(512, 1)
void hyperconv_mma(const __nv_bfloat16* __restrict__ inh,  // NHWC hi
                   const __nv_bfloat16* __restrict__ inl,  // NHWC lo
                   float* __restrict__ out,                // mode2: f32 NCHW
                   __nv_bfloat16* __restrict__ oyh,        // mode1: NHWC hi
                   __nv_bfloat16* __restrict__ oyl,        // mode1: NHWC lo
                   const __nv_bfloat16* __restrict__ wh,
                   const __nv_bfloat16* __restrict__ wl,
                   const float* __restrict__ goB, const float* __restrict__ boB,
                   const float* __restrict__ moB, const float* __restrict__ voB,
                   const float* __restrict__ addsrc,
                   int mode)
{
    extern __shared__ __align__(1024) char smem[];
    const uint32_t sbase = smem_u32(smem);

    const int tid  = threadIdx.x;
    const int wid  = tid >> 5;
    const int lane = tid & 31;
    const int h0     = blockIdx.x * 2;
    const int coBase = blockIdx.y * 128;
    const int b      = blockIdx.z;

    // staging coordinates
    const int am = tid >> 2;            // A row (co local)
    const int aq = (tid & 3) * 2;       // 16B-chunk pair
    const int px = tid & 127;           // B row (pixel)
    const int bq = tid >> 7;            // 0..3: 32B quarter of 128B row
    const int pr = px >> 6;
    const int pw = px & 63;

    // compute coordinates
    const int wm = wid & 3;
    const int wn = wid >> 2;
    const int aRow = (wm*32 + (lane & 15)) * SROWB + ((lane >> 4) << 4);
    const int bRow = (wn*32 + (lane & 7) + ((lane >> 4) << 3)) * SROWB
                   + (((lane >> 3) & 1) << 4);

    float acc[2][4][4];
    #pragma unroll
    for (int i = 0; i < 2; ++i)
        #pragma unroll
        for (int j = 0; j < 4; ++j)
            #pragma unroll
            for (int k = 0; k < 4; ++k)
                acc[i][j][k] = 0.f;

    auto issue = [&](int c, int stg) {
        const uint32_t base = sbase + stg * BUFSZ;
        const int khw = c >> 2, ci0 = (c & 3) << 6;
        // A: presynth weights, contiguous
        {
            const size_t rowbase =
                (((size_t)b * 9 + khw) * 256 + coBase + am) * 256 + ci0;
            const char* srcH = (const char*)(wh + rowbase) + aq * 16;
            const char* srcL = (const char*)(wl + rowbase) + aq * 16;
            const uint32_t dH = base + AHI_O + am*SROWB + aq*16;
            const uint32_t dL = base + ALO_O + am*SROWB + aq*16;
            CP16(dH,      srcH);
            CP16(dH + 16, srcH + 16);
            CP16(dL,      srcL);
            CP16(dL + 16, srcL + 16);
        }
        // B: NHWC activations, 128B row per pixel, zero-fill halo
        {
            const int dh = khw / 3 - 1;
            const int dw = khw - (khw / 3) * 3 - 1;
            const int hh = h0 + pr + dh;
            const int wp = pw + dw;
            const bool valid = ((unsigned)hh < HH) && ((unsigned)wp < WW);
            const int hc = valid ? hh : 0;
            const int wc = valid ? wp : 0;
            const uint32_t n = valid ? 16u : 0u;
            const size_t gofs = ((((size_t)b*HH + hc)*WW + wc)*256 + ci0);
            const char* srcH = (const char*)(inh + gofs) + bq * 32;
            const char* srcL = (const char*)(inl + gofs) + bq * 32;
            const uint32_t dH = base + BHI_O + px*SROWB + bq*32;
            const uint32_t dL = base + BLO_O + px*SROWB + bq*32;
            CP16Z(dH,      srcH,      n);
            CP16Z(dH + 16, srcH + 16, n);
            CP16Z(dL,      srcL,      n);
            CP16Z(dL + 16, srcL + 16, n);
        }
        CP_COMMIT();
    };

    auto compute = [&](int stg) {
        const uint32_t base = sbase + stg * BUFSZ;
        #pragma unroll
        for (int s = 0; s < 4; ++s) {
            uint32_t ah[2][4], al[2][4], bh[2][4], bl[2][4];
            #pragma unroll
            for (int mi = 0; mi < 2; ++mi) {
                const uint32_t ao = base + aRow + mi*(16*SROWB) + s*32;
                ldsm4(ah[mi], ao + AHI_O);
                ldsm4(al[mi], ao + ALO_O);
            }
            #pragma unroll
            for (int nj = 0; nj < 2; ++nj) {
                const uint32_t bo = base + bRow + nj*(16*SROWB) + s*32;
                ldsm4(bh[nj], bo + BHI_O);
                ldsm4(bl[nj], bo + BLO_O);
            }
            #pragma unroll
            for (int mi = 0; mi < 2; ++mi)
                #pragma unroll
                for (int nf = 0; nf < 4; ++nf) {
                    const uint32_t* bhp = &bh[nf >> 1][(nf & 1) * 2];
                    const uint32_t* blp = &bl[nf >> 1][(nf & 1) * 2];
                    mma16816(acc[mi][nf], ah[mi], bhp);
                    mma16816(acc[mi][nf], ah[mi], blp);
                    mma16816(acc[mi][nf], al[mi], bhp);
                }
        }
    };

    // 3-stage pipeline
    issue(0, 0);
    issue(1, 1);
    for (int c = 0; c < 36; ++c) {
        if (c == 35) { CP_WAIT0(); } else { CP_WAIT1(); }
        __syncthreads();
        if (c + 2 < 36) issue(c + 2, (c + 2) % NSTG);
        compute(c % NSTG);
    }

    // ---------------- epilogue ----------------
    const int g  = lane >> 2;
    const int qt = lane & 3;

    if (mode == 1) {
        // bn2+relu, split bf16 hi/lo, SMEM transpose -> NHWC planes
        __syncthreads();
        uint16_t* eh = (uint16_t*)(smem);            // [n][co] row 272B
        uint16_t* el = (uint16_t*)(smem + 36864);
        #pragma unroll
        for (int mi = 0; mi < 2; ++mi) {
            #pragma unroll
            for (int rh = 0; rh < 2; ++rh) {
                const int co_l = wm*32 + mi*16 + rh*8 + g;
                const int gco  = coBase + co_l;
                float inv = goB[gco] * rsqrtf(voB[gco] + 1e-5f);
                float sh  = boB[gco] - moB[gco] * inv;
                #pragma unroll
                for (int nf = 0; nf < 4; ++nf) {
                    const int n = wn*32 + (nf >> 1)*16 + (nf & 1)*8 + qt*2;
                    float o0 = fmaxf(fmaf(acc[mi][nf][rh*2+0], inv, sh), 0.f);
                    float o1 = fmaxf(fmaf(acc[mi][nf][rh*2+1], inv, sh), 0.f);
                    uint16_t h16, l16;
                    split1(o0, h16, l16);
                    eh[(size_t)n*136 + co_l] = h16;
                    el[(size_t)n*136 + co_l] = l16;
                    split1(o1, h16, l16);
                    eh[(size_t)(n+1)*136 + co_l] = h16;
                    el[(size_t)(n+1)*136 + co_l] = l16;
                }
            }
        }
        __syncthreads();
        {
            const int n = tid >> 2, q = tid & 3;   // n row, 64B quarter
            const int h = h0 + (n >> 6);
            const int w = n & 63;
            const size_t gofs = ((((size_t)b*HH + h)*WW + w)*256 + coBase);
            const char* sh_ = (const char*)eh + n*272 + q*64;
            const char* sl_ = (const char*)el + n*272 + q*64;
            char* gh = (char*)(oyh + gofs) + q*64;
            char* gl = (char*)(oyl + gofs) + q*64;
            #pragma unroll
            for (int j = 0; j < 4; ++j) {
                *(uint4*)(gh + j*16) = *(const uint4*)(sh_ + j*16);
                *(uint4*)(gl + j*16) = *(const uint4*)(sl_ + j*16);
            }
        }
    } else {
        // + residual, f32 NCHW
        #pragma unroll
        for (int mi = 0; mi < 2; ++mi) {
            #pragma unroll
            for (int rh = 0; rh < 2; ++rh) {
                const int gco = coBase + wm*32 + mi*16 + rh*8 + g;
                #pragma unroll
                for (int nf = 0; nf < 4; ++nf) {
                    const int n = wn*32 + (nf >> 1)*16 + (nf & 1)*8 + qt*2;
                    const int h = h0 + (n >> 6);
                    const int w = n & 63;
                    const size_t idx = (((size_t)b*CC + gco)*HH + h)*WW + w;
                    float2 xv = *(const float2*)(addsrc + idx);
                    float2 o;
                    o.x = acc[mi][nf][rh*2+0] + xv.x;
                    o.y = acc[mi][nf][rh*2+1] + xv.y;
                    *(float2*)(out + idx) = o;
                }
            }
        }
    }
}

// ---------------- launcher ----------------
extern "C" void kernel_launch(void* const* d_in, const int* in_sizes, int n_in,
                              void* d_out, int out_size)
{
    const float* x    = (const float*)d_in[0];
    const float* hin  = (const float*)d_in[1];
    const float* g1   = (const float*)d_in[2];
    const float* be1  = (const float*)d_in[3];
    const float* mu1  = (const float*)d_in[4];
    const float* var1 = (const float*)d_in[5];
    const float* w1   = (const float*)d_in[6];
    const float* b1   = (const float*)d_in[7];
    const float* g2   = (const float*)d_in[8];
    const float* be2  = (const float*)d_in[9];
    const float* mu2  = (const float*)d_in[10];
    const float* var2 = (const float*)d_in[11];
    const float* w2   = (const float*)d_in[12];
    const float* b2   = (const float*)d_in[13];
    float* out = (float*)d_out;

    __nv_bfloat16 *xh, *xl, *yh, *yl, *w1h, *w1l, *w2h, *w2l;
    cudaGetSymbolAddress((void**)&xh, g_xh);
    cudaGetSymbolAddress((void**)&xl, g_xl);
    cudaGetSymbolAddress((void**)&yh, g_yh);
    cudaGetSymbolAddress((void**)&yl, g_yl);
    cudaGetSymbolAddress((void**)&w1h, g_w1h);
    cudaGetSymbolAddress((void**)&w1l, g_w1l);
    cudaGetSymbolAddress((void**)&w2h, g_w2h);
    cudaGetSymbolAddress((void**)&w2l, g_w2l);

    cudaFuncSetAttribute(hyperconv_mma,
                         cudaFuncAttributeMaxDynamicSharedMemorySize, SMEM_TOT);

    dim3 pgrid(256, 4);
    presynth_kernel<<<pgrid, 288>>>(w1, b1, hin, w1h, w1l);
    presynth_kernel<<<pgrid, 288>>>(w2, b2, hin, w2h, w2l);

    dim3 xgrid(HH, BQ);
    prep_kernel<<<xgrid, 256>>>(x, g1, be1, mu1, var1, xh, xl);

    dim3 grid(32, 2, BQ);

    // conv1: B = prep(x), epilogue bn2+relu -> NHWC hi/lo planes
    hyperconv_mma<<<grid, 512, SMEM_TOT>>>(xh, xl, nullptr, yh, yl,
                                           w1h, w1l,
                                           g2, be2, mu2, var2,
                                           nullptr, 1);

    // conv2: B = conv1 planes, epilogue + residual -> f32 out
    hyperconv_mma<<<grid, 512, SMEM_TOT>>>(yh, yl, out, nullptr, nullptr,
                                           w2h, w2l,
                                           g2, be2, mu2, var2,
                                           x, 2);
}

// round 13
// speedup vs baseline: 2.3748x; 2.3748x over previous
#include <cuda_runtime.h>
#include <cuda_fp16.h>
#include <cstdint>

#define BQ 32
#define CC 256
#define HH 64
#define WW 64

// ---------------- static scratch ----------------
__device__ __half g_xf[(size_t)BQ*HH*WW*CC];    // relu(bn1(x)) NHWC fp16
__device__ __half g_yf[(size_t)BQ*HH*WW*CC];    // conv1 out NHWC fp16
__device__ __half g_w1f[(size_t)BQ*9*CC*CC];    // per-sample weights fp16
__device__ __half g_w2f[(size_t)BQ*9*CC*CC];

// ---------------- helpers ----------------
__device__ __forceinline__ uint32_t smem_u32(const void* p) {
    uint32_t a;
    asm("{ .reg .u64 t; cvta.to.shared.u64 t, %1; cvt.u32.u64 %0, t; }" : "=r"(a) : "l"(p));
    return a;
}
__device__ __forceinline__ void ldsm4(uint32_t* r, uint32_t addr) {
    asm volatile("ldmatrix.sync.aligned.m8n8.x4.shared.b16 {%0,%1,%2,%3}, [%4];"
                 : "=r"(r[0]), "=r"(r[1]), "=r"(r[2]), "=r"(r[3]) : "r"(addr));
}
__device__ __forceinline__ void mma16816(float* d, const uint32_t* a, const uint32_t* b) {
    asm volatile("mma.sync.aligned.m16n8k16.row.col.f32.f16.f16.f32 "
                 "{%0,%1,%2,%3}, {%4,%5,%6,%7}, {%8,%9}, {%0,%1,%2,%3};"
                 : "+f"(d[0]), "+f"(d[1]), "+f"(d[2]), "+f"(d[3])
                 : "r"(a[0]), "r"(a[1]), "r"(a[2]), "r"(a[3]), "r"(b[0]), "r"(b[1]));
}
#define CP16(dst, src)     asm volatile("cp.async.cg.shared.global [%0], [%1], 16;" :: "r"(dst), "l"(src))
#define CP16Z(dst, src, n) asm volatile("cp.async.cg.shared.global [%0], [%1], 16, %2;" :: "r"(dst), "l"(src), "r"(n))
#define CP_COMMIT()        asm volatile("cp.async.commit_group;" ::: "memory")
#define CP_WAIT0()         asm volatile("cp.async.wait_group 0;" ::: "memory")
#define CP_WAIT2()         asm volatile("cp.async.wait_group 2;" ::: "memory")

// ---------------- presynth: tw[b][khw][co][ci] = hb*w + bias -> fp16 ----
__global__ __launch_bounds__(288)
void presynth_kernel(const float* __restrict__ wv, const float* __restrict__ bv,
                     const float* __restrict__ hin,
                     __half* __restrict__ of)
{
    __shared__ float sw[9*256];
    __shared__ float sbb[9*256];
    __shared__ float shb[8];
    const int co  = blockIdx.x;
    const int bg  = blockIdx.y;
    const int tid = threadIdx.x;

    for (int t = tid; t < 2304; t += 288) {
        int ciL = t / 9, khw = t - ciL * 9;
        sw[khw*256 + ciL]  = wv[co*2304 + t];
        sbb[khw*256 + ciL] = bv[co*2304 + t];
    }
    if (tid < 8) shb[tid] = 0.5f + hin[bg*8 + tid] * (1.0f/64.0f);
    __syncthreads();

    #pragma unroll 1
    for (int bi = 0; bi < 8; ++bi) {
        const int b = bg*8 + bi;
        const float hb = shb[bi];
        #pragma unroll
        for (int r = 0; r < 2; ++r) {
            int item = tid + r*288;            // 576 = 9 khw x 64 ci-quads
            int khw = item >> 6;
            int ci  = (item & 63) * 4;
            float4 w4 = *(const float4*)&sw[khw*256 + ci];
            float4 b4 = *(const float4*)&sbb[khw*256 + ci];
            __half2 p0 = __floats2half2_rn(fmaf(hb, w4.x, b4.x), fmaf(hb, w4.y, b4.y));
            __half2 p1 = __floats2half2_rn(fmaf(hb, w4.z, b4.z), fmaf(hb, w4.w, b4.w));
            size_t o = (((size_t)b*9 + khw)*256 + co)*256 + ci;
            *(uint2*)(of + o) = make_uint2(*(uint32_t*)&p0, *(uint32_t*)&p1);
        }
    }
}

// ---------------- prep: relu(bn1(x)) NCHW f32 -> NHWC fp16 ----------
__global__ __launch_bounds__(256)
void prep_kernel(const float* __restrict__ x,
                 const float* __restrict__ g1, const float* __restrict__ be1,
                 const float* __restrict__ mu1, const float* __restrict__ var1,
                 __half* __restrict__ xf)
{
    __shared__ float sInv[256], sSh[256];
    __shared__ uint16_t th[64*72];      // [w][ci_l], 144B rows
    const int h   = blockIdx.x;
    const int b   = blockIdx.y;
    const int tid = threadIdx.x;

    {
        float inv = g1[tid] * rsqrtf(var1[tid] + 1e-5f);
        sInv[tid] = inv;
        sSh[tid]  = be1[tid] - mu1[tid] * inv;
    }
    __syncthreads();

    #pragma unroll 1
    for (int g4 = 0; g4 < 4; ++g4) {
        #pragma unroll 4
        for (int rep = 0; rep < 16; ++rep) {
            const int ci_l = rep*4 + (tid >> 6);
            const int ci   = g4*64 + ci_l;
            const int w    = tid & 63;
            float v = x[(((size_t)b*256 + ci)*64 + h)*64 + w];
            v = fmaxf(fmaf(v, sInv[ci], sSh[ci]), 0.f);
            __half hv = __float2half_rn(v);
            th[w*72 + ci_l] = *(uint16_t*)&hv;
        }
        __syncthreads();
        {
            const int w = tid >> 2, q = tid & 3;       // q: 32B quarter
            const size_t gofs = ((((size_t)b*64 + h)*64 + w)*256 + g4*64);
            const char* sh_ = (const char*)th + w*144 + q*32;
            char* gh = (char*)(xf + gofs) + q*32;
            *(uint4*)(gh)      = *(const uint4*)(sh_);
            *(uint4*)(gh + 16) = *(const uint4*)(sh_ + 16);
        }
        __syncthreads();
    }
}

// ---------------- fp16 mma.sync implicit-GEMM, 4-stage cp.async ----------
#define SROWB 144
#define A_O   0
#define B_O   18432
#define BUFSZ 36864
#define NSTG  4
#define SMEM_TOT (NSTG*BUFSZ)           // 147456 B

__global__ __launch_bounds__(512, 1)
void hyperconv_mma(const __half* __restrict__ inf,   // NHWC fp16
                   float* __restrict__ out,          // mode2: f32 NCHW
                   __half* __restrict__ oyf,         // mode1: NHWC fp16
                   const __half* __restrict__ wf,
                   const float* __restrict__ goB, const float* __restrict__ boB,
                   const float* __restrict__ moB, const float* __restrict__ voB,
                   const float* __restrict__ addsrc,
                   int mode)
{
    extern __shared__ __align__(1024) char smem[];
    const uint32_t sbase = smem_u32(smem);

    const int tid  = threadIdx.x;
    const int wid  = tid >> 5;
    const int lane = tid & 31;
    const int h0     = blockIdx.x * 2;
    const int coBase = blockIdx.y * 128;
    const int b      = blockIdx.z;

    // staging coordinates
    const int am = tid >> 2;            // A row (co local)
    const int aq = tid & 3;             // 32B quarter of 128B row
    const int px = tid & 127;           // B row (pixel)
    const int bq = tid >> 7;            // 32B quarter
    const int pr = px >> 6;
    const int pw = px & 63;

    // compute coordinates
    const int wm = wid & 3;
    const int wn = wid >> 2;
    const int aRow = (wm*32 + (lane & 15)) * SROWB + ((lane >> 4) << 4);
    const int bRow = (wn*32 + (lane & 7) + ((lane >> 4) << 3)) * SROWB
                   + (((lane >> 3) & 1) << 4);

    float acc[2][4][4];
    #pragma unroll
    for (int i = 0; i < 2; ++i)
        #pragma unroll
        for (int j = 0; j < 4; ++j)
            #pragma unroll
            for (int k = 0; k < 4; ++k)
                acc[i][j][k] = 0.f;

    auto issue = [&](int c, int stg) {
        const uint32_t base = sbase + stg * BUFSZ;
        const int khw = c >> 2, ci0 = (c & 3) << 6;
        // A: presynth weights, contiguous 128B rows
        {
            const size_t rowbase =
                (((size_t)b * 9 + khw) * 256 + coBase + am) * 256 + ci0;
            const char* srcA = (const char*)(wf + rowbase) + aq * 32;
            const uint32_t dA = base + A_O + am*SROWB + aq*32;
            CP16(dA,      srcA);
            CP16(dA + 16, srcA + 16);
        }
        // B: NHWC fp16, 128B per (pixel, 64ci), zero-fill halo
        {
            const int dh = khw / 3 - 1;
            const int dw = khw - (khw / 3) * 3 - 1;
            const int hh = h0 + pr + dh;
            const int wp = pw + dw;
            const bool valid = ((unsigned)hh < HH) && ((unsigned)wp < WW);
            const int hc = valid ? hh : 0;
            const int wc = valid ? wp : 0;
            const uint32_t n = valid ? 16u : 0u;
            const size_t gofs = ((((size_t)b*HH + hc)*WW + wc)*256 + ci0);
            const char* srcB = (const char*)(inf + gofs) + bq * 32;
            const uint32_t dB = base + B_O + px*SROWB + bq*32;
            CP16Z(dB,      srcB,      n);
            CP16Z(dB + 16, srcB + 16, n);
        }
        CP_COMMIT();
    };

    auto compute = [&](int stg) {
        const uint32_t base = sbase + stg * BUFSZ;
        #pragma unroll
        for (int s = 0; s < 4; ++s) {
            uint32_t af[2][4], bf[2][4];
            #pragma unroll
            for (int mi = 0; mi < 2; ++mi)
                ldsm4(af[mi], base + A_O + aRow + mi*(16*SROWB) + s*32);
            #pragma unroll
            for (int nj = 0; nj < 2; ++nj)
                ldsm4(bf[nj], base + B_O + bRow + nj*(16*SROWB) + s*32);
            #pragma unroll
            for (int mi = 0; mi < 2; ++mi)
                #pragma unroll
                for (int nf = 0; nf < 4; ++nf)
                    mma16816(acc[mi][nf], af[mi], &bf[nf >> 1][(nf & 1) * 2]);
        }
    };

    // 4-stage pipeline, 3-chunk lookahead
    issue(0, 0);
    issue(1, 1);
    issue(2, 2);
    for (int c = 0; c < 36; ++c) {
        if (c < 33) { CP_WAIT2(); } else { CP_WAIT0(); }
        __syncthreads();
        if (c + 3 < 36) issue(c + 3, (c + 3) % NSTG);
        compute(c % NSTG);
    }

    // ---------------- epilogue ----------------
    const int g  = lane >> 2;
    const int qt = lane & 3;

    if (mode == 1) {
        // bn2+relu -> fp16, SMEM transpose -> NHWC plane
        __syncthreads();
        uint16_t* eh = (uint16_t*)(smem);     // [n][co_l], 272B rows
        #pragma unroll
        for (int mi = 0; mi < 2; ++mi) {
            #pragma unroll
            for (int rh = 0; rh < 2; ++rh) {
                const int co_l = wm*32 + mi*16 + rh*8 + g;
                const int gco  = coBase + co_l;
                float inv = goB[gco] * rsqrtf(voB[gco] + 1e-5f);
                float sh  = boB[gco] - moB[gco] * inv;
                #pragma unroll
                for (int nf = 0; nf < 4; ++nf) {
                    const int n = wn*32 + (nf >> 1)*16 + (nf & 1)*8 + qt*2;
                    float o0 = fmaxf(fmaf(acc[mi][nf][rh*2+0], inv, sh), 0.f);
                    float o1 = fmaxf(fmaf(acc[mi][nf][rh*2+1], inv, sh), 0.f);
                    __half q0 = __float2half_rn(o0);
                    __half q1 = __float2half_rn(o1);
                    eh[(size_t)n*136 + co_l]     = *(uint16_t*)&q0;
                    eh[(size_t)(n+1)*136 + co_l] = *(uint16_t*)&q1;
                }
            }
        }
        __syncthreads();
        {
            const int n = tid >> 2, q = tid & 3;   // q: 64B quarter of 256B
            const int h = h0 + (n >> 6);
            const int w = n & 63;
            const size_t gofs = ((((size_t)b*HH + h)*WW + w)*256 + coBase);
            const char* sh_ = (const char*)eh + n*272 + q*64;
            char* gh = (char*)(oyf + gofs) + q*64;
            #pragma unroll
            for (int j = 0; j < 4; ++j)
                *(uint4*)(gh + j*16) = *(const uint4*)(sh_ + j*16);
        }
    } else {
        // + residual, f32 NCHW
        #pragma unroll
        for (int mi = 0; mi < 2; ++mi) {
            #pragma unroll
            for (int rh = 0; rh < 2; ++rh) {
                const int gco = coBase + wm*32 + mi*16 + rh*8 + g;
                #pragma unroll
                for (int nf = 0; nf < 4; ++nf) {
                    const int n = wn*32 + (nf >> 1)*16 + (nf & 1)*8 + qt*2;
                    const int h = h0 + (n >> 6);
                    const int w = n & 63;
                    const size_t idx = (((size_t)b*CC + gco)*HH + h)*WW + w;
                    float2 xv = *(const float2*)(addsrc + idx);
                    float2 o;
                    o.x = acc[mi][nf][rh*2+0] + xv.x;
                    o.y = acc[mi][nf][rh*2+1] + xv.y;
                    *(float2*)(out + idx) = o;
                }
            }
        }
    }
}

// ---------------- launcher ----------------
extern "C" void kernel_launch(void* const* d_in, const int* in_sizes, int n_in,
                              void* d_out, int out_size)
{
    const float* x    = (const float*)d_in[0];
    const float* hin  = (const float*)d_in[1];
    const float* g1   = (const float*)d_in[2];
    const float* be1  = (const float*)d_in[3];
    const float* mu1  = (const float*)d_in[4];
    const float* var1 = (const float*)d_in[5];
    const float* w1   = (const float*)d_in[6];
    const float* b1   = (const float*)d_in[7];
    const float* g2   = (const float*)d_in[8];
    const float* be2  = (const float*)d_in[9];
    const float* mu2  = (const float*)d_in[10];
    const float* var2 = (const float*)d_in[11];
    const float* w2   = (const float*)d_in[12];
    const float* b2   = (const float*)d_in[13];
    float* out = (float*)d_out;

    __half *xf, *yf, *w1f, *w2f;
    cudaGetSymbolAddress((void**)&xf, g_xf);
    cudaGetSymbolAddress((void**)&yf, g_yf);
    cudaGetSymbolAddress((void**)&w1f, g_w1f);
    cudaGetSymbolAddress((void**)&w2f, g_w2f);

    cudaFuncSetAttribute(hyperconv_mma,
                         cudaFuncAttributeMaxDynamicSharedMemorySize, SMEM_TOT);

    dim3 pgrid(256, 4);
    presynth_kernel<<<pgrid, 288>>>(w1, b1, hin, w1f);
    presynth_kernel<<<pgrid, 288>>>(w2, b2, hin, w2f);

    dim3 xgrid(HH, BQ);
    prep_kernel<<<xgrid, 256>>>(x, g1, be1, mu1, var1, xf);

    dim3 grid(32, 2, BQ);

    // conv1: B = prep(x), epilogue bn2+relu -> NHWC fp16
    hyperconv_mma<<<grid, 512, SMEM_TOT>>>(xf, nullptr, yf, w1f,
                                           g2, be2, mu2, var2,
                                           nullptr, 1);

    // conv2: B = conv1 plane, epilogue + residual -> f32 out
    hyperconv_mma<<<grid, 512, SMEM_TOT>>>(yf, out, nullptr, w2f,
                                           g2, be2, mu2, var2,
                                           x, 2);
}